// round 1
// baseline (speedup 1.0000x reference)
#include <cuda_runtime.h>
#include <cuda_bf16.h>

// SqRL: square rotational unrolling gather.
// x: (BC, 512, 512) fp32  ->  out: (BC, 256, 2048) fp32
// For ring index r (= dif), i = 255 - r, el = 2r+1 (H even), the output row is:
//   [ (i,i) x i | top edge el | (i,511-i) x 2i | right edge el | (i+el,i+el) x 2i |
//     bottom edge el (rev) | (i+el,i) x 2i | left edge el (rev) | (i,i) x i | wrap 4 ]
// Total 8i + 4el = 2044, then entries [0:4) repeated at [2044:2048).

#define HH      512
#define HR      256
#define ROWLEN  2048
#define WRAPJ   2044

__global__ __launch_bounds__(256)
void sqrl_gather_kernel(const float* __restrict__ x, float* __restrict__ out) {
    const int r  = blockIdx.y;            // dif: 0..255
    const int bc = blockIdx.z;            // image index: 0..511
    const int i  = (HR - 1) - r;          // 255 - r
    const int el = 2 * r + 1;
    const int b1 = i + el;                // = 256 + r  (also row/col of bottom-right corner)
    const int twoi = 2 * i;
    const int b2 = b1 + twoi;
    const int b3 = b2 + el;
    const int b4 = b3 + twoi;
    const int b5 = b4 + el;
    const int b6 = b5 + twoi;
    const int b7 = b6 + el;               // b7 + i == 2044

    const int jbase = blockIdx.x * 1024 + threadIdx.x * 4;
    const float* __restrict__ img = x + (size_t)bc * (HH * HH);

    float4 v;
    float* vp = reinterpret_cast<float*>(&v);

    #pragma unroll
    for (int k = 0; k < 4; ++k) {
        int jp = jbase + k;
        if (jp >= WRAPJ) jp -= WRAPJ;     // tail wrap: cols [2044,2048) copy [0,4)
        int row, col;
        if (jp < i)        { row = i;                 col = i;                 } // TL corner
        else if (jp < b1)  { row = i;                 col = jp;                } // top edge
        else if (jp < b2)  { row = i;                 col = HH - 1 - i;        } // TR corner
        else if (jp < b3)  { row = i + (jp - b2);     col = HH - 1 - i;        } // right edge
        else if (jp < b4)  { row = b1;                col = b1;                } // BR corner
        else if (jp < b5)  { row = b1;                col = b1 - (jp - b4);    } // bottom edge (rev)
        else if (jp < b6)  { row = b1;                col = i;                 } // BL corner
        else if (jp < b7)  { row = b1 - (jp - b6);    col = i;                 } // left edge (rev)
        else               { row = i;                 col = i;                 } // TL corner again
        vp[k] = __ldg(img + row * HH + col);
    }

    const size_t o = (((size_t)bc * HR) + (size_t)r) * ROWLEN + (size_t)jbase;
    *reinterpret_cast<float4*>(out + o) = v;
}

extern "C" void kernel_launch(void* const* d_in, const int* in_sizes, int n_in,
                              void* d_out, int out_size) {
    const float* x = (const float*)d_in[0];
    float* out = (float*)d_out;
    const int bc = in_sizes[0] / (HH * HH);   // 16*32 = 512 images
    // Grid ordered so consecutive CTAs share one image (L2 locality):
    // x = half-row j tile (2), y = ring r (256), z = image (512).
    dim3 grid(2, HR, bc);
    sqrl_gather_kernel<<<grid, 256>>>(x, out);
}